// round 3
// baseline (speedup 1.0000x reference)
#include <cuda_runtime.h>

#define E_EDGES 400000
#define TILE 128
#define NTHR 256

// ---------------- scratch (__device__ globals: allocation-free) ----------------
__device__ float g_xp2[(size_t)E_EDGES * 128];   // silu(x1@w_p2.T+b)   [E,128]
__device__ float g_t  [(size_t)E_EDGES * 64];    // silu(x_p4@w_down.T) [E,64]
__device__ float g_wt [194048];                  // folded+transposed weights (k-major)

// float offsets inside g_wt
#define WT_P2   0        // [128][128]
#define WT_P4   16384    // [128][128]
#define WT_SBFC 32768    // [44][128]  (folded w_sbf2@w_sbf1, rows 42..43 zero)
#define WT_DOWN 38400    // [128][64]
#define WT_TC   46592    // [296][64]  (folded w_t2@w_t1, rows 294..295 zero)
#define WT_UP   65536    // [64][128]
#define WT_RB1  73728    // [128][128]
#define WT_RB2  90112    // [128][128]
#define WT_LIN  106496   // [128][128]
#define WT_RA1  122880   // [2][128][128]
#define WT_RA2  155648   // [2][128][128]
#define WT_SBF  188416   // [44][128]  (w_sbf transposed, rows 42..43 zero)

typedef unsigned long long u64;

__device__ __forceinline__ float siluf(float x) {
    return __fdividef(x, 1.0f + __expf(-x));
}
__device__ __forceinline__ u64 pk2(float x, float y) {
    u64 r; asm("mov.b64 %0,{%1,%2};" : "=l"(r) : "f"(x), "f"(y)); return r;
}
__device__ __forceinline__ float2 upk2(u64 v) {
    float2 r; asm("mov.b64 {%0,%1},%2;" : "=f"(r.x), "=f"(r.y) : "l"(v)); return r;
}
__device__ __forceinline__ void ffma2(u64 &a, u64 x, u64 y) {
    asm("fma.rn.f32x2 %0,%1,%2,%0;" : "+l"(a) : "l"(x), "l"(y));
}

// ---------------- setup: fold rank-8 factors, transpose all weights to k-major ----------------
__global__ void setup_kernel(
    const float* __restrict__ w_p2, const float* __restrict__ w_p4,
    const float* __restrict__ w_sbf1, const float* __restrict__ w_sbf2,
    const float* __restrict__ w_t1, const float* __restrict__ w_t2,
    const float* __restrict__ w_down, const float* __restrict__ w_up,
    const float* __restrict__ rb_w1, const float* __restrict__ rb_w2,
    const float* __restrict__ w_lin,
    const float* __restrict__ ra_w1, const float* __restrict__ ra_w2,
    const float* __restrict__ w_sbf)
{
    int tid = blockIdx.x * blockDim.x + threadIdx.x;
    int nt = gridDim.x * blockDim.x;
    for (int i = tid; i < 16384; i += nt) {
        int k = i >> 7, j = i & 127;
        g_wt[WT_P2 + i]  = w_p2[j * 128 + k];
        g_wt[WT_P4 + i]  = w_p4[j * 128 + k];
        g_wt[WT_RB1 + i] = rb_w1[j * 128 + k];
        g_wt[WT_RB2 + i] = rb_w2[j * 128 + k];
        g_wt[WT_LIN + i] = w_lin[j * 128 + k];
        g_wt[WT_RA1 + i]          = ra_w1[j * 128 + k];
        g_wt[WT_RA1 + 16384 + i]  = ra_w1[16384 + j * 128 + k];
        g_wt[WT_RA2 + i]          = ra_w2[j * 128 + k];
        g_wt[WT_RA2 + 16384 + i]  = ra_w2[16384 + j * 128 + k];
    }
    for (int i = tid; i < 8192; i += nt) {   // w_down [64,128] -> [128][64]
        int k = i >> 6, j = i & 63;
        g_wt[WT_DOWN + i] = w_down[j * 128 + k];
    }
    for (int i = tid; i < 8192; i += nt) {   // w_up [128,64] -> [64][128]
        int k = i >> 7, j = i & 127;
        g_wt[WT_UP + i] = w_up[j * 64 + k];
    }
    for (int i = tid; i < 44 * 128; i += nt) { // folded sbf: C[j][k]=sum_b w_sbf2[j][b]*w_sbf1[b][k] -> [k][j]
        int k = i >> 7, j = i & 127; float v = 0.f;
        if (k < 42) {
            #pragma unroll
            for (int b = 0; b < 8; b++) v += w_sbf2[j * 8 + b] * w_sbf1[b * 42 + k];
        }
        g_wt[WT_SBFC + i] = v;
    }
    for (int i = tid; i < 44 * 128; i += nt) { // w_sbf [128,42] -> [44][128]
        int k = i >> 7, j = i & 127;
        g_wt[WT_SBF + i] = (k < 42) ? w_sbf[j * 42 + k] : 0.f;
    }
    for (int i = tid; i < 296 * 64; i += nt) { // folded t: T[j][k]=sum_b w_t2[j][b]*w_t1[b][k] -> [k][j]
        int k = i >> 6, j = i & 63; float v = 0.f;
        if (k < 294) {
            #pragma unroll
            for (int b = 0; b < 8; b++) v += w_t2[j * 8 + b] * w_t1[b * 294 + k];
        }
        g_wt[WT_TC + i] = v;
    }
}

// ---------------- GEMM micro-kernels (f32x2 packed FFMA) ----------------
// As: smem [128 rows][stride 128], row-major.  Ws: smem [K][N] k-major.
// Thread (tx in 0..15, ty in 0..15): rows ty*8..+7.
// N=128: cols tx*8..+7 (acc[8][4] f32x2 pairs). N=64: cols tx*4..+3 (acc[8][2]).

__device__ __forceinline__ void gemm_n128(const float* __restrict__ As,
                                          const float* __restrict__ Ws,
                                          int K, u64 acc[8][4], int tx, int ty)
{
    const float* arow = As + ty * 8 * 128;
    const float* wc = Ws + tx * 8;
    for (int k = 0; k < K; k += 4) {
        u64 bp[4][4];
        #pragma unroll
        for (int kk = 0; kk < 4; kk++) {
            float4 b0 = *(const float4*)(wc + (k + kk) * 128);
            float4 b1 = *(const float4*)(wc + (k + kk) * 128 + 4);
            bp[kk][0] = pk2(b0.x, b0.y); bp[kk][1] = pk2(b0.z, b0.w);
            bp[kk][2] = pk2(b1.x, b1.y); bp[kk][3] = pk2(b1.z, b1.w);
        }
        #pragma unroll
        for (int u = 0; u < 8; u++) {
            float4 a4 = *(const float4*)(arow + u * 128 + k);
            u64 ad0 = pk2(a4.x, a4.x), ad1 = pk2(a4.y, a4.y);
            u64 ad2 = pk2(a4.z, a4.z), ad3 = pk2(a4.w, a4.w);
            #pragma unroll
            for (int p = 0; p < 4; p++) ffma2(acc[u][p], ad0, bp[0][p]);
            #pragma unroll
            for (int p = 0; p < 4; p++) ffma2(acc[u][p], ad1, bp[1][p]);
            #pragma unroll
            for (int p = 0; p < 4; p++) ffma2(acc[u][p], ad2, bp[2][p]);
            #pragma unroll
            for (int p = 0; p < 4; p++) ffma2(acc[u][p], ad3, bp[3][p]);
        }
    }
}

__device__ __forceinline__ void gemm_n64(const float* __restrict__ As,
                                         const float* __restrict__ Ws,
                                         int K, u64 acc[8][2], int tx, int ty)
{
    const float* arow = As + ty * 8 * 128;
    const float* wc = Ws + tx * 4;
    for (int k = 0; k < K; k += 4) {
        u64 bp[4][2];
        #pragma unroll
        for (int kk = 0; kk < 4; kk++) {
            float4 b = *(const float4*)(wc + (k + kk) * 64);
            bp[kk][0] = pk2(b.x, b.y); bp[kk][1] = pk2(b.z, b.w);
        }
        #pragma unroll
        for (int u = 0; u < 8; u++) {
            float4 a4 = *(const float4*)(arow + u * 128 + k);
            u64 ad0 = pk2(a4.x, a4.x), ad1 = pk2(a4.y, a4.y);
            u64 ad2 = pk2(a4.z, a4.z), ad3 = pk2(a4.w, a4.w);
            ffma2(acc[u][0], ad0, bp[0][0]); ffma2(acc[u][1], ad0, bp[0][1]);
            ffma2(acc[u][0], ad1, bp[1][0]); ffma2(acc[u][1], ad1, bp[1][1]);
            ffma2(acc[u][0], ad2, bp[2][0]); ffma2(acc[u][1], ad2, bp[2][1]);
            ffma2(acc[u][0], ad3, bp[3][0]); ffma2(acc[u][1], ad3, bp[3][1]);
        }
    }
}

__device__ __forceinline__ void acc_bias128(u64 acc[8][4], const float* __restrict__ b, int tx) {
    float4 b0 = *(const float4*)(b + tx * 8);
    float4 b1 = *(const float4*)(b + tx * 8 + 4);
    u64 p0 = pk2(b0.x, b0.y), p1 = pk2(b0.z, b0.w);
    u64 p2 = pk2(b1.x, b1.y), p3 = pk2(b1.z, b1.w);
    #pragma unroll
    for (int u = 0; u < 8; u++) { acc[u][0] = p0; acc[u][1] = p1; acc[u][2] = p2; acc[u][3] = p3; }
}
__device__ __forceinline__ void acc_zero128(u64 acc[8][4]) {
    #pragma unroll
    for (int u = 0; u < 8; u++) { acc[u][0] = 0ull; acc[u][1] = 0ull; acc[u][2] = 0ull; acc[u][3] = 0ull; }
}
__device__ __forceinline__ void acc_zero64(u64 acc[8][2]) {
    #pragma unroll
    for (int u = 0; u < 8; u++) { acc[u][0] = 0ull; acc[u][1] = 0ull; }
}

// ---------------- staging helpers (all coalesced float4/float2) ----------------
__device__ __forceinline__ void stage_f4(float* dst, const float* __restrict__ src, int nf4) {
    const float4* s = (const float4*)src;
    float4* d = (float4*)dst;
    for (int i = threadIdx.x; i < nf4; i += NTHR) d[i] = s[i];
}
// sbf0 tile (row stride 42) -> smem [128][stride 128], cols 42..43 zeroed
__device__ __forceinline__ void stage_sbf(float* dst, const float* __restrict__ src) {
    for (int i = threadIdx.x; i < 128 * 22; i += NTHR) {
        int r = i / 22, c2 = i % 22;
        float2 v = (c2 < 21) ? *(const float2*)(src + (size_t)r * 42 + 2 * c2)
                             : make_float2(0.f, 0.f);
        *(float2*)(dst + r * 128 + 2 * c2) = v;
    }
}
// ta chunk (row stride 294) -> smem [128][stride 128], kc cols (kvalid real, rest zero)
__device__ __forceinline__ void stage_ta(float* dst, const float* __restrict__ src, int kc, int kvalid) {
    int c2n = kc >> 1;
    for (int i = threadIdx.x; i < 128 * c2n; i += NTHR) {
        int r = i / c2n, c2 = i % c2n;
        float2 v = (2 * c2 < kvalid) ? *(const float2*)(src + (size_t)r * 294 + 2 * c2)
                                     : make_float2(0.f, 0.f);
        *(float2*)(dst + r * 128 + 2 * c2) = v;
    }
}

// ---------------- Kernel A: x_p2 -> gmem;  t = silu((silu(x1@Wp4)*sbf)@Wdown) -> gmem ----------------
extern "C" __global__ void __launch_bounds__(NTHR, 1)
kernelA(const float* __restrict__ x1, const float* __restrict__ sbf0,
        const float* __restrict__ b_p2, const float* __restrict__ b_p4)
{
    extern __shared__ float sm[];
    float* A1 = sm;
    float* WB = sm + 16384;
    float* C  = sm + 32768;
    int tx = threadIdx.x & 15, ty = threadIdx.x >> 4;
    int r0 = blockIdx.x * TILE;

    stage_f4(A1, x1 + (size_t)r0 * 128, 4096);
    stage_f4(WB, g_wt + WT_P2, 4096);
    __syncthreads();

    u64 acc[8][4];
    // ---- x_p2 = silu(x1@Wp2 + b) -> g_xp2
    acc_bias128(acc, b_p2, tx);
    gemm_n128(A1, WB, 128, acc, tx, ty);
    #pragma unroll
    for (int u = 0; u < 8; u++) {
        size_t rg = (size_t)(r0 + ty * 8 + u) * 128 + tx * 8;
        float2 v0 = upk2(acc[u][0]), v1 = upk2(acc[u][1]), v2 = upk2(acc[u][2]), v3 = upk2(acc[u][3]);
        *(float4*)(g_xp2 + rg)     = make_float4(siluf(v0.x), siluf(v0.y), siluf(v1.x), siluf(v1.y));
        *(float4*)(g_xp2 + rg + 4) = make_float4(siluf(v2.x), siluf(v2.y), siluf(v3.x), siluf(v3.y));
    }
    __syncthreads();
    stage_f4(WB, g_wt + WT_P4, 4096);
    __syncthreads();

    // ---- silu(x1@Wp4 + b) -> C
    acc_bias128(acc, b_p4, tx);
    gemm_n128(A1, WB, 128, acc, tx, ty);
    #pragma unroll
    for (int u = 0; u < 8; u++) {
        int rs = (ty * 8 + u) * 128 + tx * 8;
        float2 v0 = upk2(acc[u][0]), v1 = upk2(acc[u][1]), v2 = upk2(acc[u][2]), v3 = upk2(acc[u][3]);
        *(float4*)(C + rs)     = make_float4(siluf(v0.x), siluf(v0.y), siluf(v1.x), siluf(v1.y));
        *(float4*)(C + rs + 4) = make_float4(siluf(v2.x), siluf(v2.y), siluf(v3.x), siluf(v3.y));
    }
    __syncthreads();

    // ---- sbf = sbf0 @ WsbfC  (K=44 padded)
    stage_sbf(A1, sbf0 + (size_t)r0 * 42);
    stage_f4(WB, g_wt + WT_SBFC, 1408);
    __syncthreads();
    acc_zero128(acc);
    gemm_n128(A1, WB, 44, acc, tx, ty);
    __syncthreads();   // all done reading A1 (sbf0) before overwrite
    #pragma unroll
    for (int u = 0; u < 8; u++) {
        int rs = (ty * 8 + u) * 128 + tx * 8;
        float4 c0 = *(const float4*)(C + rs);
        float4 c1 = *(const float4*)(C + rs + 4);
        float2 v0 = upk2(acc[u][0]), v1 = upk2(acc[u][1]), v2 = upk2(acc[u][2]), v3 = upk2(acc[u][3]);
        *(float4*)(A1 + rs)     = make_float4(v0.x * c0.x, v0.y * c0.y, v1.x * c0.z, v1.y * c0.w);
        *(float4*)(A1 + rs + 4) = make_float4(v2.x * c1.x, v2.y * c1.y, v3.x * c1.z, v3.y * c1.w);
    }
    stage_f4(WB, g_wt + WT_DOWN, 2048);
    __syncthreads();

    // ---- t = silu(x_p4 @ Wdown)  (N=64) -> g_t
    u64 acc2[8][2];
    acc_zero64(acc2);
    gemm_n64(A1, WB, 128, acc2, tx, ty);
    #pragma unroll
    for (int u = 0; u < 8; u++) {
        size_t rg = (size_t)(r0 + ty * 8 + u) * 64 + tx * 4;
        float2 v0 = upk2(acc2[u][0]), v1 = upk2(acc2[u][1]);
        *(float4*)(g_t + rg) = make_float4(siluf(v0.x), siluf(v0.y), siluf(v1.x), siluf(v1.y));
    }
}

// ---------------- residual block on smem P ----------------
__device__ __forceinline__ void resblock(float* P, float* A1, float* WB,
                                         const float* __restrict__ wt1, const float* __restrict__ b1,
                                         const float* __restrict__ wt2, const float* __restrict__ b2,
                                         int tx, int ty)
{
    __syncthreads();
    stage_f4(WB, wt1, 4096);
    __syncthreads();
    u64 acc[8][4];
    acc_bias128(acc, b1, tx);
    gemm_n128(P, WB, 128, acc, tx, ty);
    __syncthreads();
    #pragma unroll
    for (int u = 0; u < 8; u++) {
        int rs = (ty * 8 + u) * 128 + tx * 8;
        float2 v0 = upk2(acc[u][0]), v1 = upk2(acc[u][1]), v2 = upk2(acc[u][2]), v3 = upk2(acc[u][3]);
        *(float4*)(A1 + rs)     = make_float4(siluf(v0.x), siluf(v0.y), siluf(v1.x), siluf(v1.y));
        *(float4*)(A1 + rs + 4) = make_float4(siluf(v2.x), siluf(v2.y), siluf(v3.x), siluf(v3.y));
    }
    stage_f4(WB, wt2, 4096);
    __syncthreads();
    acc_bias128(acc, b2, tx);
    gemm_n128(A1, WB, 128, acc, tx, ty);
    #pragma unroll
    for (int u = 0; u < 8; u++) {
        int rs = (ty * 8 + u) * 128 + tx * 8;
        float4 p0 = *(const float4*)(P + rs);
        float4 p1 = *(const float4*)(P + rs + 4);
        float2 v0 = upk2(acc[u][0]), v1 = upk2(acc[u][1]), v2 = upk2(acc[u][2]), v3 = upk2(acc[u][3]);
        *(float4*)(P + rs)     = make_float4(p0.x + siluf(v0.x), p0.y + siluf(v0.y),
                                             p0.z + siluf(v1.x), p0.w + siluf(v1.y));
        *(float4*)(P + rs + 4) = make_float4(p1.x + siluf(v2.x), p1.y + siluf(v2.y),
                                             p1.z + siluf(v3.x), p1.w + siluf(v3.y));
    }
}

// ---------------- Kernel B: ta GEMM, gather-mul, up-proj, residual tail, outputs ----------------
extern "C" __global__ void __launch_bounds__(NTHR, 1)
kernelB(const float* __restrict__ ta, const float* __restrict__ sbf0,
        const int* __restrict__ p_idx, const float* __restrict__ x1,
        const float* __restrict__ rb_b1, const float* __restrict__ rb_b2,
        const float* __restrict__ b_lin,
        const float* __restrict__ ra_b1, const float* __restrict__ ra_b2,
        float* __restrict__ out)
{
    extern __shared__ float sm[];
    float* A1 = sm;
    float* WB = sm + 16384;
    float* P  = sm + 32768;
    int tx = threadIdx.x & 15, ty = threadIdx.x >> 4;
    int r0 = blockIdx.x * TILE;

    // ---- ta_p = ta @ WtC  (K=294 in chunks 128/128/40(pad))
    u64 acc2[8][2];
    acc_zero64(acc2);
    const int k0s[3] = {0, 128, 256};
    const int kcs[3] = {128, 128, 40};
    const int kvs[3] = {128, 128, 38};
    for (int c = 0; c < 3; c++) {
        __syncthreads();
        stage_ta(A1, ta + (size_t)r0 * 294 + k0s[c], kcs[c], kvs[c]);
        stage_f4(WB, g_wt + WT_TC + k0s[c] * 64, kcs[c] * 16);
        __syncthreads();
        gemm_n64(A1, WB, kcs[c], acc2, tx, ty);
    }
    __syncthreads();

    // ---- g = t[p_idx] * ta_p -> A1 cols 0..63
    #pragma unroll
    for (int u = 0; u < 8; u++) {
        int r = r0 + ty * 8 + u;
        int idx = p_idx[r];
        float4 g = *(const float4*)(g_t + (size_t)idx * 64 + tx * 4);
        float2 t0 = upk2(acc2[u][0]), t1 = upk2(acc2[u][1]);
        *(float4*)(A1 + (ty * 8 + u) * 128 + tx * 4) =
            make_float4(t0.x * g.x, t0.y * g.y, t1.x * g.z, t1.y * g.w);
    }
    stage_f4(WB, g_wt + WT_UP, 2048);
    __syncthreads();

    // ---- p1 = silu(g @ Wup) + x_p2 -> P
    u64 acc[8][4];
    acc_zero128(acc);
    gemm_n128(A1, WB, 64, acc, tx, ty);
    #pragma unroll
    for (int u = 0; u < 8; u++) {
        size_t rg = (size_t)(r0 + ty * 8 + u) * 128 + tx * 8;
        int rs = (ty * 8 + u) * 128 + tx * 8;
        float4 x0 = *(const float4*)(g_xp2 + rg);
        float4 x1v = *(const float4*)(g_xp2 + rg + 4);
        float2 v0 = upk2(acc[u][0]), v1 = upk2(acc[u][1]), v2 = upk2(acc[u][2]), v3 = upk2(acc[u][3]);
        *(float4*)(P + rs)     = make_float4(x0.x + siluf(v0.x), x0.y + siluf(v0.y),
                                             x0.z + siluf(v1.x), x0.w + siluf(v1.y));
        *(float4*)(P + rs + 4) = make_float4(x1v.x + siluf(v2.x), x1v.y + siluf(v2.y),
                                             x1v.z + siluf(v3.x), x1v.w + siluf(v3.y));
    }

    // ---- res-before (1 block)
    resblock(P, A1, WB, g_wt + WT_RB1, rb_b1, g_wt + WT_RB2, rb_b2, tx, ty);

    // ---- p1 = silu(p1@Wlin + b) + x1
    __syncthreads();
    stage_f4(WB, g_wt + WT_LIN, 4096);
    __syncthreads();
    acc_bias128(acc, b_lin, tx);
    gemm_n128(P, WB, 128, acc, tx, ty);
    #pragma unroll
    for (int u = 0; u < 8; u++) {
        size_t rg = (size_t)(r0 + ty * 8 + u) * 128 + tx * 8;
        int rs = (ty * 8 + u) * 128 + tx * 8;
        float4 x0 = *(const float4*)(x1 + rg);
        float4 x1v = *(const float4*)(x1 + rg + 4);
        float2 v0 = upk2(acc[u][0]), v1 = upk2(acc[u][1]), v2 = upk2(acc[u][2]), v3 = upk2(acc[u][3]);
        *(float4*)(P + rs)     = make_float4(x0.x + siluf(v0.x), x0.y + siluf(v0.y),
                                             x0.z + siluf(v1.x), x0.w + siluf(v1.y));
        *(float4*)(P + rs + 4) = make_float4(x1v.x + siluf(v2.x), x1v.y + siluf(v2.y),
                                             x1v.z + siluf(v3.x), x1v.w + siluf(v3.y));
    }

    // ---- res-after (2 blocks)
    resblock(P, A1, WB, g_wt + WT_RA1,         ra_b1,       g_wt + WT_RA2,         ra_b2,       tx, ty);
    resblock(P, A1, WB, g_wt + WT_RA1 + 16384, ra_b1 + 128, g_wt + WT_RA2 + 16384, ra_b2 + 128, tx, ty);

    __syncthreads();
    // ---- write p1 (contiguous tile copy)
    {
        const float4* s = (const float4*)P;
        float4* d = (float4*)(out + (size_t)r0 * 128);
        for (int i = threadIdx.x; i < 4096; i += NTHR) d[i] = s[i];
    }
    // ---- p2 = (sbf0 @ Wsbf) * p1
    stage_sbf(A1, sbf0 + (size_t)r0 * 42);
    stage_f4(WB, g_wt + WT_SBF, 1408);
    __syncthreads();
    acc_zero128(acc);
    gemm_n128(A1, WB, 44, acc, tx, ty);
    float* out2 = out + (size_t)E_EDGES * 128;
    #pragma unroll
    for (int u = 0; u < 8; u++) {
        size_t rg = (size_t)(r0 + ty * 8 + u) * 128 + tx * 8;
        int rs = (ty * 8 + u) * 128 + tx * 8;
        float4 p0 = *(const float4*)(P + rs);
        float4 p1v = *(const float4*)(P + rs + 4);
        float2 v0 = upk2(acc[u][0]), v1 = upk2(acc[u][1]), v2 = upk2(acc[u][2]), v3 = upk2(acc[u][3]);
        *(float4*)(out2 + rg)     = make_float4(v0.x * p0.x, v0.y * p0.y, v1.x * p0.z, v1.y * p0.w);
        *(float4*)(out2 + rg + 4) = make_float4(v2.x * p1v.x, v2.y * p1v.y, v3.x * p1v.z, v3.y * p1v.w);
    }
}

// ---------------- launch ----------------
extern "C" void kernel_launch(void* const* d_in, const int* in_sizes, int n_in,
                              void* d_out, int out_size)
{
    const float* x1     = (const float*)d_in[0];
    const float* sbf0   = (const float*)d_in[1];
    const float* ta     = (const float*)d_in[2];
    const int*   p_idx  = (const int*)  d_in[3];
    const float* w_p2   = (const float*)d_in[4];
    const float* b_p2   = (const float*)d_in[5];
    const float* w_p4   = (const float*)d_in[6];
    const float* b_p4   = (const float*)d_in[7];
    const float* w_sbf1 = (const float*)d_in[8];
    const float* w_sbf2 = (const float*)d_in[9];
    const float* w_t1   = (const float*)d_in[10];
    const float* w_t2   = (const float*)d_in[11];
    const float* w_down = (const float*)d_in[12];
    const float* w_up   = (const float*)d_in[13];
    const float* rb_w1  = (const float*)d_in[14];
    const float* rb_b1  = (const float*)d_in[15];
    const float* rb_w2  = (const float*)d_in[16];
    const float* rb_b2  = (const float*)d_in[17];
    const float* w_lin  = (const float*)d_in[18];
    const float* b_lin  = (const float*)d_in[19];
    const float* ra_w1  = (const float*)d_in[20];
    const float* ra_b1  = (const float*)d_in[21];
    const float* ra_w2  = (const float*)d_in[22];
    const float* ra_b2  = (const float*)d_in[23];
    const float* w_sbf  = (const float*)d_in[24];
    float* out = (float*)d_out;

    const int SMEM = 3 * 16384 * (int)sizeof(float); // 192 KB
    cudaFuncSetAttribute(kernelA, cudaFuncAttributeMaxDynamicSharedMemorySize, SMEM);
    cudaFuncSetAttribute(kernelB, cudaFuncAttributeMaxDynamicSharedMemorySize, SMEM);

    setup_kernel<<<128, 256>>>(w_p2, w_p4, w_sbf1, w_sbf2, w_t1, w_t2, w_down, w_up,
                               rb_w1, rb_w2, w_lin, ra_w1, ra_w2, w_sbf);
    kernelA<<<E_EDGES / TILE, NTHR, SMEM>>>(x1, sbf0, b_p2, b_p4);
    kernelB<<<E_EDGES / TILE, NTHR, SMEM>>>(ta, sbf0, p_idx, x1,
                                            rb_b1, rb_b2, b_lin, ra_b1, ra_b2, out);
}